// round 11
// baseline (speedup 1.0000x reference)
#include <cuda_runtime.h>

// SSIM loss, fused single kernel (separable 11-tap Gaussian).
// img1, img2: [16,3,512,512] fp32. Output: scalar mean of SSIM map.
// R11: end-to-end f32x2 lane packing of (u,d)=(x+y,x-y). All three phases keep
//      the pair packed: phase1 stores (u,d) float2; phase2 convolves packed
//      (one task/quad, FFMA2); phase3 vertical conv on packed columns.
//      32x64 tiles, 512 threads, 3 CTAs/SM.

typedef unsigned long long u64;

constexpr int IMG_H = 512;
constexpr int IMG_W = 512;
constexpr int NPLANES = 48;              // 16 * 3
constexpr int TILE_W = 32;
constexpr int TILE_H = 64;
constexpr int HALO = 5;
constexpr int IN_W = TILE_W + 2 * HALO;  // 42
constexpr int IN_H = TILE_H + 2 * HALO;  // 74
constexpr int UD_STRIDE = 44;            // pairs per input row (16B-friendly)
constexpr int H_STRIDE = 32;             // pairs per map row
constexpr int MAPSZ = IN_H * H_STRIDE;   // 2368 pairs per packed map
constexpr int NTHREADS = 512;
constexpr int GRID_X = IMG_W / TILE_W;   // 16
constexpr int GRID_Y = IMG_H / TILE_H;   // 8
constexpr int NBLOCKS = GRID_X * GRID_Y * NPLANES;  // 6144
constexpr int NQUAD = IN_H * (TILE_W / 4);          // 592 phase-2 tasks
// smem (in u64 pairs): UD tile + 2 packed maps
constexpr int UD_PAIRS = IN_H * UD_STRIDE;          // 3256
constexpr int SMEM_PAIRS = UD_PAIRS + 2 * MAPSZ;    // 7992 pairs = 63936 B
constexpr float C1f = 0.0001f;
constexpr float C2f = 0.0009f;

// Gaussian(sigma=1.5) 1D weights as f32x2 (both lanes equal).
__constant__ u64 G2[11] = {
    0x3A86CAB53A86CAB5ull,  // 0.00102838
    0x3BF8FF053BF8FF05ull,  // 0.00759876
    0x3D13758B3D13758Bull,  // 0.03600077
    0x3DDFF87F3DDFF87Full,  // 0.10936070
    0x3E5A1DE03E5A1DE0ull,  // 0.21300460
    0x3E8832B03E8832B0ull,  // 0.26601170
    0x3E5A1DE03E5A1DE0ull,
    0x3DDFF87F3DDFF87Full,
    0x3D13758B3D13758Bull,
    0x3BF8FF053BF8FF05ull,
    0x3A86CAB53A86CAB5ull
};

__device__ float g_partial[NBLOCKS];
__device__ unsigned int g_count;   // starts 0 (BSS), self-resets each call

__device__ __forceinline__ u64 fma2(u64 a, u64 b, u64 c) {
    u64 d;
    asm("fma.rn.f32x2 %0, %1, %2, %3;" : "=l"(d) : "l"(a), "l"(b), "l"(c));
    return d;
}
__device__ __forceinline__ u64 mul2(u64 a, u64 b) {
    u64 d;
    asm("mul.rn.f32x2 %0, %1, %2;" : "=l"(d) : "l"(a), "l"(b));
    return d;
}
__device__ __forceinline__ void unpack2(u64 v, float& lo, float& hi) {
    asm("mov.b64 {%0, %1}, %2;" : "=f"(lo), "=f"(hi) : "l"(v));
}

__global__ void __launch_bounds__(NTHREADS, 3)
ssim_main_kernel(const float* __restrict__ img1, const float* __restrict__ img2,
                 float* __restrict__ out) {
    extern __shared__ u64 sm8[];
    u64* sUD = sm8;                 // [IN_H][UD_STRIDE] packed (u,d)
    u64* sHA = sm8 + UD_PAIRS;      // [IN_H][H_STRIDE]  packed (cu,  cd)
    u64* sHB = sHA + MAPSZ;         // [IN_H][H_STRIDE]  packed (cu2, cd2)

    const int tid = threadIdx.x;

    // ---- Phase 1: load input tiles, store packed (u,d) (zero halo at edges) ----
    // 504 threads: thread = (r0 = tid/42 in 0..11, c = tid%42); rows r0 + 12k.
    if (tid < 504) {
        const int plane = blockIdx.z;
        const int ty = blockIdx.y * TILE_H;
        const int tx = blockIdx.x * TILE_W;
        const float* p1 = img1 + (size_t)plane * IMG_H * IMG_W;
        const float* p2 = img2 + (size_t)plane * IMG_H * IMG_W;
        const int r0 = tid / IN_W;
        const int c = tid - r0 * IN_W;
        const int gx = tx + c - HALO;
        const bool cin = (unsigned)gx < (unsigned)IMG_W;
        const float* c1 = p1 + gx;
        const float* c2 = p2 + gx;
        float2* dud = reinterpret_cast<float2*>(sUD) + r0 * UD_STRIDE + c;
#pragma unroll
        for (int k = 0; k < 7; k++) {
            const int r = r0 + 12 * k;
            if (r < IN_H) {
                const int gy = ty + r - HALO;
                float v1 = 0.f, v2 = 0.f;
                if (cin & ((unsigned)gy < (unsigned)IMG_H)) {
                    v1 = __ldg(c1 + gy * IMG_W);
                    v2 = __ldg(c2 + gy * IMG_W);
                }
                dud[12 * k * UD_STRIDE] = make_float2(v1 + v2, v1 - v2);
            }
        }
    }
    __syncthreads();

    // ---- Phase 2: horizontal conv, fully packed. Task = row-quad (592). ----
    for (int t = tid; t < NQUAD; t += NTHREADS) {
        const int r = t >> 3;                 // 8 quads per row
        const int c0 = (t & 7) << 2;
        const ulonglong2* src16 =
            reinterpret_cast<const ulonglong2*>(sUD + r * UD_STRIDE + c0);
        u64 w[14];
#pragma unroll
        for (int i = 0; i < 7; i++) {
            ulonglong2 v = src16[i];
            w[2 * i] = v.x;
            w[2 * i + 1] = v.y;
        }
        // conv of (u,d)
        u64 acc[4];
#pragma unroll
        for (int k = 0; k < 4; k++) {
            u64 s = 0ull;
#pragma unroll
            for (int j = 0; j < 11; j++) s = fma2(G2[j], w[k + j], s);
            acc[k] = s;
        }
        ulonglong2* dstA = reinterpret_cast<ulonglong2*>(sHA + r * H_STRIDE + c0);
        dstA[0] = make_ulonglong2(acc[0], acc[1]);
        dstA[1] = make_ulonglong2(acc[2], acc[3]);
        // conv of (u^2, d^2)
#pragma unroll
        for (int i = 0; i < 14; i++) w[i] = mul2(w[i], w[i]);
#pragma unroll
        for (int k = 0; k < 4; k++) {
            u64 s = 0ull;
#pragma unroll
            for (int j = 0; j < 11; j++) s = fma2(G2[j], w[k + j], s);
            acc[k] = s;
        }
        ulonglong2* dstB = reinterpret_cast<ulonglong2*>(sHB + r * H_STRIDE + c0);
        dstB[0] = make_ulonglong2(acc[0], acc[1]);
        dstB[1] = make_ulonglong2(acc[2], acc[3]);
    }
    __syncthreads();

    // ---- Phase 3: vertical conv on packed columns (4-row strip, 512 tasks) ----
    float lsum = 0.f;
    {
        const int c = tid & 31;
        const int r0 = (tid >> 5) * 4;                // 16 strips of 4 rows
        const u64* colA = sHA + r0 * H_STRIDE + c;
        const u64* colB = sHB + r0 * H_STRIDE + c;
        u64 aA[4], aB[4];
#pragma unroll
        for (int k = 0; k < 4; k++) { aA[k] = 0ull; aB[k] = 0ull; }
#pragma unroll
        for (int i = 0; i < 14; i++) {
            u64 vA = colA[i * H_STRIDE];
            u64 vB = colB[i * H_STRIDE];
#pragma unroll
            for (int ro = 0; ro < 4; ro++) {
                const int j = i - ro;
                if (j >= 0 && j < 11) {               // compile-time resolved
                    aA[ro] = fma2(G2[j], vA, aA[ro]);
                    aB[ro] = fma2(G2[j], vB, aB[ro]);
                }
            }
        }
#pragma unroll
        for (int ro = 0; ro < 4; ro++) {
            float cu, cd, cu2, cd2;
            unpack2(aA[ro], cu, cd);
            unpack2(aB[ro], cu2, cd2);
            float A = cu * cu;                                 // (mu1+mu2)^2
            float B = cd * cd;                                 // (mu1-mu2)^2
            float t1 = 0.5f * (A - B) + C1f;                   // 2*mu1*mu2 + C1
            float t2 = 0.5f * ((cu2 - cd2) - (A - B)) + C2f;   // 2*sigma12 + C2
            float t3 = 0.5f * (A + B) + C1f;                   // mu1^2+mu2^2 + C1
            float t4 = 0.5f * ((cu2 + cd2) - (A + B)) + C2f;   // sx+sy + C2
            lsum += __fdividef(t1 * t2, t3 * t4);
        }
    }

    // ---- Block reduce (fp32) ----
    __shared__ float wsum[NTHREADS / 32];
#pragma unroll
    for (int o = 16; o > 0; o >>= 1) lsum += __shfl_xor_sync(0xFFFFFFFFu, lsum, o);
    if ((tid & 31) == 0) wsum[tid >> 5] = lsum;
    __syncthreads();

    __shared__ bool isLast;
    if (tid == 0) {
        const int bid = (blockIdx.z * GRID_Y + blockIdx.y) * GRID_X + blockIdx.x;
        float s = 0.f;
#pragma unroll
        for (int i = 0; i < NTHREADS / 32; i++) s += wsum[i];
        g_partial[bid] = s;
        __threadfence();
        unsigned int old = atomicAdd(&g_count, 1u);
        isLast = (old == (unsigned)(NBLOCKS - 1));
    }
    __syncthreads();

    // ---- Last block: final reduction in double ----
    if (isLast) {
        double d = 0.0;
        for (int k = 0; k < NBLOCKS / NTHREADS; k++)
            d += (double)g_partial[tid + k * NTHREADS];
#pragma unroll
        for (int o = 16; o > 0; o >>= 1) d += __shfl_xor_sync(0xFFFFFFFFu, d, o);
        __shared__ double dsum[NTHREADS / 32];
        if ((tid & 31) == 0) dsum[tid >> 5] = d;
        __syncthreads();
        if (tid == 0) {
            double s = 0.0;
#pragma unroll
            for (int i = 0; i < NTHREADS / 32; i++) s += dsum[i];
            out[0] = (float)(s / (double)((size_t)NPLANES * IMG_H * IMG_W));
            g_count = 0;   // self-reset for next graph replay
        }
    }
}

extern "C" void kernel_launch(void* const* d_in, const int* in_sizes, int n_in,
                              void* d_out, int out_size) {
    const float* img1 = (const float*)d_in[0];
    const float* img2 = (const float*)d_in[1];
    float* out = (float*)d_out;

    cudaFuncSetAttribute(ssim_main_kernel,
                         cudaFuncAttributeMaxDynamicSharedMemorySize,
                         SMEM_PAIRS * (int)sizeof(u64));

    dim3 grid(GRID_X, GRID_Y, NPLANES);
    ssim_main_kernel<<<grid, NTHREADS, SMEM_PAIRS * sizeof(u64)>>>(img1, img2, out);
}

// round 12
// speedup vs baseline: 1.3039x; 1.3039x over previous
#include <cuda_runtime.h>

// SSIM loss, fused single kernel (separable 11-tap Gaussian).
// img1, img2: [16,3,512,512] fp32. Output: scalar mean of SSIM map.
// R12: R10 base (u/d transform, scalar FFMA-imm convs, 32x64 tiles, 512 thr,
//      3 CTAs/SM) + interleaved float4 H-map [cu,cu2,cd,cd2] with padded row
//      stride -> phase 3 reads 14 LDS.128 instead of 56 LDS.32.

constexpr int IMG_H = 512;
constexpr int IMG_W = 512;
constexpr int NPLANES = 48;              // 16 * 3
constexpr int TILE_W = 32;
constexpr int TILE_H = 64;
constexpr int HALO = 5;
constexpr int IN_W = TILE_W + 2 * HALO;  // 42
constexpr int IN_H = TILE_H + 2 * HALO;  // 74
constexpr int IMG_STRIDE = 44;           // padded row stride for u/d tiles
constexpr int H_STRIDE4 = 33;            // H-map row stride in float4 units (528B: bank-spread)
constexpr int NTHREADS = 512;
constexpr int GRID_X = IMG_W / TILE_W;   // 16
constexpr int GRID_Y = IMG_H / TILE_H;   // 8
constexpr int NBLOCKS = GRID_X * GRID_Y * NPLANES;  // 6144
constexpr int NQUAD = IN_H * (TILE_W / 4);          // 592 row-quads per group
constexpr int NTASK2 = NQUAD * 2;                   // 1184 phase-2 tasks
// smem: two scalar u/d tiles + one interleaved float4 map
constexpr int SMEM_FLOATS = 2 * IN_H * IMG_STRIDE + IN_H * H_STRIDE4 * 4;  // 6512+9768=16280 (~65.1KB)
constexpr float C1f = 0.0001f;
constexpr float C2f = 0.0009f;

// Gaussian(sigma=1.5) 1D weights, normalized (w2d = outer(g,g))
__device__ constexpr float G[11] = {
    0.00102838f, 0.00759876f, 0.03600077f, 0.10936070f, 0.21300460f,
    0.26601170f,
    0.21300460f, 0.10936070f, 0.03600077f, 0.00759876f, 0.00102838f
};

__device__ float g_partial[NBLOCKS];
__device__ unsigned int g_count;   // starts 0 (BSS), self-resets each call

// 11-tap horizontal conv of a 14-float window -> 4 outputs (weights fold to FFMA-imm)
__device__ __forceinline__ void conv_row4(const float* __restrict__ w, float* __restrict__ acc) {
#pragma unroll
    for (int k = 0; k < 4; k++) {
        float s = 0.f;
#pragma unroll
        for (int j = 0; j < 11; j++) s = fmaf(G[j], w[k + j], s);
        acc[k] = s;
    }
}

__device__ __forceinline__ void load16(const float* __restrict__ src, float* __restrict__ w) {
    const float4* s4 = reinterpret_cast<const float4*>(src);
#pragma unroll
    for (int i = 0; i < 4; i++) {
        float4 v = s4[i];
        w[4 * i + 0] = v.x; w[4 * i + 1] = v.y; w[4 * i + 2] = v.z; w[4 * i + 3] = v.w;
    }
}

__global__ void __launch_bounds__(NTHREADS, 3)
ssim_main_kernel(const float* __restrict__ img1, const float* __restrict__ img2,
                 float* __restrict__ out) {
    extern __shared__ float sm[];
    float* su = sm;                           // [IN_H][IMG_STRIDE]  u = x + y
    float* sd = sm + IN_H * IMG_STRIDE;       //                      d = x - y
    float* sH = sm + 2 * IN_H * IMG_STRIDE;   // [IN_H][H_STRIDE4] float4 = (cu,cu2,cd,cd2)

    const int tid = threadIdx.x;

    // ---- Phase 1: load input tiles as u/d (zero halo at image edges) ----
    // 504 threads: thread = (r0 = tid/42 in 0..11, c = tid%42); rows r0 + 12k.
    if (tid < 504) {
        const int plane = blockIdx.z;
        const int ty = blockIdx.y * TILE_H;
        const int tx = blockIdx.x * TILE_W;
        const float* p1 = img1 + (size_t)plane * IMG_H * IMG_W;
        const float* p2 = img2 + (size_t)plane * IMG_H * IMG_W;
        const int r0 = tid / IN_W;
        const int c = tid - r0 * IN_W;
        const int gx = tx + c - HALO;
        const bool cin = (unsigned)gx < (unsigned)IMG_W;
        const float* c1 = p1 + gx;
        const float* c2 = p2 + gx;
        float* du = su + r0 * IMG_STRIDE + c;
        float* dd = sd + r0 * IMG_STRIDE + c;
#pragma unroll
        for (int k = 0; k < 7; k++) {
            const int r = r0 + 12 * k;
            if (r < IN_H) {
                const int gy = ty + r - HALO;
                float v1 = 0.f, v2 = 0.f;
                if (cin & ((unsigned)gy < (unsigned)IMG_H)) {
                    v1 = __ldg(c1 + gy * IMG_W);
                    v2 = __ldg(c2 + gy * IMG_W);
                }
                du[12 * k * IMG_STRIDE] = v1 + v2;
                dd[12 * k * IMG_STRIDE] = v1 - v2;
            }
        }
    }
    __syncthreads();

    // ---- Phase 2: horizontal conv. Task = (row-quad, group).
    // group 0: (cu,cu2) from su -> float4 lanes .x/.y; group 1: (cd,cd2) -> .z/.w.
    // 1184 tasks / 512 threads. Each task: 4 LDS.128 + 88 FFMA + 14 FMUL + 4 STS.64.
    for (int t = tid; t < NTASK2; t += NTHREADS) {
        int ro = t;
        int goff = 0;
        if (ro >= NQUAD) { ro -= NQUAD; goff = 1; }
        int r = ro >> 3;                      // 8 quads per row
        int c0 = (ro & 7) << 2;
        const float* src = su + goff * (IN_H * IMG_STRIDE) + r * IMG_STRIDE + c0;
        float w[16], accA[4], accB[4];
        load16(src, w);
        conv_row4(w, accA);                                   // cu or cd
#pragma unroll
        for (int i = 0; i < 14; i++) w[i] = w[i] * w[i];
        conv_row4(w, accB);                                   // cu2 or cd2
        // store (accA[k], accB[k]) into float4 halves
        float2* dst = reinterpret_cast<float2*>(sH + (r * H_STRIDE4 + c0) * 4) + goff;
#pragma unroll
        for (int k = 0; k < 4; k++)
            dst[2 * k] = make_float2(accA[k], accB[k]);
    }
    __syncthreads();

    // ---- Phase 3: vertical conv (4-row strip per thread, exactly 512 tasks).
    // One LDS.128 per input row fetches all 4 map values (contiguous per warp).
    float lsum = 0.f;
    {
        const int c = tid & 31;
        const int r0 = (tid >> 5) * 4;                // 16 strips of 4 rows
        float a0[4], a1[4], a2[4], a3[4];             // cu, cu2, cd, cd2
#pragma unroll
        for (int k = 0; k < 4; k++) { a0[k] = 0.f; a1[k] = 0.f; a2[k] = 0.f; a3[k] = 0.f; }
        const float4* col = reinterpret_cast<const float4*>(sH) + r0 * H_STRIDE4 + c;
#pragma unroll
        for (int i = 0; i < 14; i++) {
            float4 v = col[i * H_STRIDE4];
#pragma unroll
            for (int ro = 0; ro < 4; ro++) {
                const int j = i - ro;
                if (j >= 0 && j < 11) {               // compile-time resolved
                    a0[ro] = fmaf(G[j], v.x, a0[ro]);
                    a1[ro] = fmaf(G[j], v.y, a1[ro]);
                    a2[ro] = fmaf(G[j], v.z, a2[ro]);
                    a3[ro] = fmaf(G[j], v.w, a3[ro]);
                }
            }
        }
#pragma unroll
        for (int ro = 0; ro < 4; ro++) {
            float cu = a0[ro], cu2 = a1[ro], cd = a2[ro], cd2 = a3[ro];
            float A = cu * cu;                                 // (mu1+mu2)^2
            float B = cd * cd;                                 // (mu1-mu2)^2
            float t1 = 0.5f * (A - B) + C1f;                   // 2*mu1*mu2 + C1
            float t2 = 0.5f * ((cu2 - cd2) - (A - B)) + C2f;   // 2*sigma12 + C2
            float t3 = 0.5f * (A + B) + C1f;                   // mu1^2+mu2^2 + C1
            float t4 = 0.5f * ((cu2 + cd2) - (A + B)) + C2f;   // sx+sy + C2
            lsum += __fdividef(t1 * t2, t3 * t4);
        }
    }

    // ---- Block reduce (fp32) ----
    __shared__ float wsum[NTHREADS / 32];
#pragma unroll
    for (int o = 16; o > 0; o >>= 1) lsum += __shfl_xor_sync(0xFFFFFFFFu, lsum, o);
    if ((tid & 31) == 0) wsum[tid >> 5] = lsum;
    __syncthreads();

    __shared__ bool isLast;
    if (tid == 0) {
        const int bid = (blockIdx.z * GRID_Y + blockIdx.y) * GRID_X + blockIdx.x;
        float s = 0.f;
#pragma unroll
        for (int i = 0; i < NTHREADS / 32; i++) s += wsum[i];
        g_partial[bid] = s;
        __threadfence();
        unsigned int old = atomicAdd(&g_count, 1u);
        isLast = (old == (unsigned)(NBLOCKS - 1));
    }
    __syncthreads();

    // ---- Last block: final reduction in double ----
    if (isLast) {
        double d = 0.0;
        for (int k = 0; k < NBLOCKS / NTHREADS; k++)
            d += (double)g_partial[tid + k * NTHREADS];
#pragma unroll
        for (int o = 16; o > 0; o >>= 1) d += __shfl_xor_sync(0xFFFFFFFFu, d, o);
        __shared__ double dsum[NTHREADS / 32];
        if ((tid & 31) == 0) dsum[tid >> 5] = d;
        __syncthreads();
        if (tid == 0) {
            double s = 0.0;
#pragma unroll
            for (int i = 0; i < NTHREADS / 32; i++) s += dsum[i];
            out[0] = (float)(s / (double)((size_t)NPLANES * IMG_H * IMG_W));
            g_count = 0;   // self-reset for next graph replay
        }
    }
}

extern "C" void kernel_launch(void* const* d_in, const int* in_sizes, int n_in,
                              void* d_out, int out_size) {
    const float* img1 = (const float*)d_in[0];
    const float* img2 = (const float*)d_in[1];
    float* out = (float*)d_out;

    cudaFuncSetAttribute(ssim_main_kernel,
                         cudaFuncAttributeMaxDynamicSharedMemorySize,
                         SMEM_FLOATS * (int)sizeof(float));

    dim3 grid(GRID_X, GRID_Y, NPLANES);
    ssim_main_kernel<<<grid, NTHREADS, SMEM_FLOATS * sizeof(float)>>>(img1, img2, out);
}